// round 1
// baseline (speedup 1.0000x reference)
#include <cuda_runtime.h>
#include <math.h>

// Problem constants
#define Bq 128
#define Uq 256
#define Dq 256
#define NG 1280   // 5*U

// ---------------- scratch (static device globals; no allocation) -------------
__device__ float g_gsum[Bq * NG];                    // pre-activation gates (B,5U)
__device__ float g_c  [Bq * Uq];
__device__ float g_fre[Bq * Uq];
__device__ float g_ste[Bq * Uq];
__device__ float g_cos[Bq * Uq];
__device__ float g_sin[Bq * Uq];
__device__ float g_AT [(size_t)Bq * Uq * Uq];        // A transposed: [b][k][u], 33.5 MB

__device__ __forceinline__ float hsig(float v) {
    return fminf(fmaxf(0.2f * v + 0.5f, 0.0f), 1.0f);
}

// ============================================================================
// Kernel 1: g_gsum = x @ kernel + z_prev @ recur_k + bias   (128 x 1280)
// 64x64 tiles, 256 threads, 4x4 per-thread tile.
// ============================================================================
__global__ __launch_bounds__(256) void k_gates_gemm(
    const float* __restrict__ x, const float* __restrict__ z_prev,
    const float* __restrict__ kern, const float* __restrict__ recur,
    const float* __restrict__ bias)
{
    __shared__ float sX[16][68];   // LHS tile transposed: [u][b]
    __shared__ float sW[16][64];

    const int tid = threadIdx.x;
    const int j0  = blockIdx.x * 64;
    const int b0  = blockIdx.y * 64;
    const int rg  = tid >> 4;      // 16 row groups * 4 rows
    const int cg  = tid & 15;      // 16 col groups * 4 cols

    float acc[4][4];
#pragma unroll
    for (int i = 0; i < 4; i++)
#pragma unroll
        for (int j = 0; j < 4; j++) acc[i][j] = 0.f;

#pragma unroll
    for (int pass = 0; pass < 2; pass++) {
        const float* L = pass ? z_prev : x;       // (128, 256)
        const float* W = pass ? recur  : kern;    // (256, 1280)
        for (int d0 = 0; d0 < 256; d0 += 16) {
            // load LHS 64x16 tile (transposed into smem): 256 float4 loads
            {
                const int lb = tid >> 2;
                const int lu = (tid & 3) * 4;
                float4 v = *(const float4*)&L[(b0 + lb) * 256 + d0 + lu];
                sX[lu + 0][lb] = v.x; sX[lu + 1][lb] = v.y;
                sX[lu + 2][lb] = v.z; sX[lu + 3][lb] = v.w;
            }
            // load W 16x64 tile
            {
                const int wu = tid >> 4;
                const int wc = (tid & 15) * 4;
                *(float4*)&sW[wu][wc] = *(const float4*)&W[(d0 + wu) * NG + j0 + wc];
            }
            __syncthreads();
#pragma unroll
            for (int kk = 0; kk < 16; kk++) {
                float a[4], bb[4];
#pragma unroll
                for (int i = 0; i < 4; i++) a[i] = sX[kk][rg * 4 + i];
#pragma unroll
                for (int j = 0; j < 4; j++) bb[j] = sW[kk][cg * 4 + j];
#pragma unroll
                for (int i = 0; i < 4; i++)
#pragma unroll
                    for (int j = 0; j < 4; j++) acc[i][j] += a[i] * bb[j];
            }
            __syncthreads();
        }
    }

#pragma unroll
    for (int i = 0; i < 4; i++) {
        const int b = b0 + rg * 4 + i;
#pragma unroll
        for (int j = 0; j < 4; j++) {
            const int jj = j0 + cg * 4 + j;
            g_gsum[b * NG + jj] = acc[i][j] + bias[jj];
        }
    }
}

// ============================================================================
// Kernel 2: elementwise gates + omega output + cos/sin(theta)
// ============================================================================
__global__ __launch_bounds__(256) void k_gates_ew(
    const float* __restrict__ omg_prev, const float* __restrict__ t,
    float* __restrict__ out_omg)
{
    const int idx = blockIdx.x * blockDim.x + threadIdx.x;   // B*U = 32768
    const int b = idx >> 8;            // / 256
    const int u = idx & 255;
    const float* g = &g_gsum[b * NG];

    const float i_g = hsig(g[u]);
    const float fre = hsig(g[Uq + u]);
    const float ste = hsig(g[2 * Uq + u]);
    const float gg  = tanhf(g[3 * Uq + u]);
    const float omg = g[4 * Uq + u];

    g_c[idx]   = i_g * gg;
    g_fre[idx] = fre;
    g_ste[idx] = ste;

    const float th = omg_prev[idx] * t[b];
    g_cos[idx] = cosf(th);
    g_sin[idx] = sinf(th);

    out_omg[idx] = omg;
}

// ============================================================================
// Kernel 3: Re/Im update + A = sqrt(Re^2+Im^2), A written transposed [b][k][u]
// Block handles one b and a 64(i) x 64(j) tile; smem tile for the transpose.
// ============================================================================
__global__ __launch_bounds__(256) void k_reim(
    const float* __restrict__ Re_prev, const float* __restrict__ Im_prev,
    float* __restrict__ Im_out, float* __restrict__ Re_out)
{
    __shared__ float sA[64][65];
    const int b  = blockIdx.z;
    const int i0 = blockIdx.y * 64;
    const int j0 = blockIdx.x * 64;
    const int tj = threadIdx.x & 63;    // j within tile
    const int ti = threadIdx.x >> 6;    // 0..3

    const float fre_j = g_fre[b * Uq + j0 + tj];
    const float cosj  = g_cos[b * Uq + j0 + tj];
    const float sinj  = g_sin[b * Uq + j0 + tj];

#pragma unroll
    for (int r = 0; r < 16; r++) {
        const int i = ti + r * 4;                 // 0..63
        const float ste_i = g_ste[b * Uq + i0 + i];
        const float ci    = g_c  [b * Uq + i0 + i];
        const size_t idx = ((size_t)b * Uq + (i0 + i)) * Uq + j0 + tj;
        const float f  = ste_i * fre_j;
        const float re = f * Re_prev[idx] + ci * cosj;
        const float im = f * Im_prev[idx] + ci * sinj;
        Re_out[idx] = re;
        Im_out[idx] = im;
        sA[i][tj] = sqrtf(re * re + im * im);
    }
    __syncthreads();
    // A_T[b][j][i] = A[b][i][j]  (coalesced over i)
#pragma unroll
    for (int r = 0; r < 16; r++) {
        const int j = ti + r * 4;
        g_AT[((size_t)b * Uq + (j0 + j)) * Uq + i0 + tj] = sA[tj][j];
    }
}

// ============================================================================
// Kernel 4: per-k fused GEMMs + epilogue + k-reduction into z.
//   acc_o = A_k @ U_o[k] + x @ W_o[k] + z_prev @ V_o[k]
//   acc_z = A_k @ W_z[k]
//   z[b,v] += hsig(acc_o + b_o[k,v]) * tanh(acc_z + b_z[k,v])
// Block = (k, v-tile of 64). 128x64 output tile, 256 threads, 8x4 per thread.
// ============================================================================
__global__ __launch_bounds__(256, 2) void k_freq(
    const float* __restrict__ x_in, const float* __restrict__ z_prev,
    const float* __restrict__ freq_k, const float* __restrict__ freq_k_input,
    const float* __restrict__ freq_bias,
    float* __restrict__ z_out)
{
    __shared__ float sA [16][132];
    __shared__ float sB1[16][64];
    __shared__ float sB2[16][64];

    const int tid = threadIdx.x;
    const int k   = blockIdx.x;
    const int v0  = blockIdx.y * 64;
    const int rg  = tid >> 4;    // 16 row groups * 8 rows
    const int cg  = tid & 15;    // 16 col groups * 4 cols

    float acc_o[8][4];
    float acc_z[8][4];
#pragma unroll
    for (int i = 0; i < 8; i++)
#pragma unroll
        for (int j = 0; j < 4; j++) { acc_o[i][j] = 0.f; acc_z[i][j] = 0.f; }

    const float* Uo = freq_k + (size_t)k * (768 * 256);        // rows u, stride 768
    const float* Wo = freq_k_input + (size_t)k * (256 * 256);  // rows d, stride 256

    // ---------------- Phase 1: A_k @ [U_o | W_z] (two accumulator sets) ------
    for (int ku = 0; ku < 256; ku += 16) {
#pragma unroll
        for (int i = 0; i < 2; i++) {
            const int e  = tid + i * 256;          // 0..511
            const int lb = e >> 2;                 // b 0..127
            const int lu = (e & 3) * 4;
            float4 v = *(const float4*)&g_AT[((size_t)lb * 256 + k) * 256 + ku + lu];
            sA[lu + 0][lb] = v.x; sA[lu + 1][lb] = v.y;
            sA[lu + 2][lb] = v.z; sA[lu + 3][lb] = v.w;
        }
        {
            const int wu = tid >> 4;
            const int wc = (tid & 15) * 4;
            *(float4*)&sB1[wu][wc] = *(const float4*)&Uo[(ku + wu) * 768 + v0 + wc];        // U_o
            *(float4*)&sB2[wu][wc] = *(const float4*)&Uo[(ku + wu) * 768 + 512 + v0 + wc];  // W_z
        }
        __syncthreads();
#pragma unroll
        for (int kk = 0; kk < 16; kk++) {
            float a[8], b1[4], b2[4];
#pragma unroll
            for (int i = 0; i < 8; i++) a[i] = sA[kk][rg * 8 + i];
#pragma unroll
            for (int j = 0; j < 4; j++) { b1[j] = sB1[kk][cg * 4 + j]; b2[j] = sB2[kk][cg * 4 + j]; }
#pragma unroll
            for (int i = 0; i < 8; i++)
#pragma unroll
                for (int j = 0; j < 4; j++) {
                    acc_o[i][j] += a[i] * b1[j];
                    acc_z[i][j] += a[i] * b2[j];
                }
        }
        __syncthreads();
    }

    // ---------------- Phase 2: x @ W_o ; Phase 3: z_prev @ V_o ---------------
#pragma unroll
    for (int phase = 0; phase < 2; phase++) {
        const float* L = phase ? z_prev : x_in;
        for (int ku = 0; ku < 256; ku += 16) {
#pragma unroll
            for (int i = 0; i < 2; i++) {
                const int e  = tid + i * 256;
                const int lb = e >> 2;
                const int lu = (e & 3) * 4;
                float4 v = *(const float4*)&L[lb * 256 + ku + lu];
                sA[lu + 0][lb] = v.x; sA[lu + 1][lb] = v.y;
                sA[lu + 2][lb] = v.z; sA[lu + 3][lb] = v.w;
            }
            {
                const int wu = tid >> 4;
                const int wc = (tid & 15) * 4;
                float4 wv;
                if (phase)
                    wv = *(const float4*)&Uo[(ku + wu) * 768 + 256 + v0 + wc];   // V_o
                else
                    wv = *(const float4*)&Wo[(ku + wu) * 256 + v0 + wc];         // W_o
                *(float4*)&sB1[wu][wc] = wv;
            }
            __syncthreads();
#pragma unroll
            for (int kk = 0; kk < 16; kk++) {
                float a[8], b1[4];
#pragma unroll
                for (int i = 0; i < 8; i++) a[i] = sA[kk][rg * 8 + i];
#pragma unroll
                for (int j = 0; j < 4; j++) b1[j] = sB1[kk][cg * 4 + j];
#pragma unroll
                for (int i = 0; i < 8; i++)
#pragma unroll
                    for (int j = 0; j < 4; j++) acc_o[i][j] += a[i] * b1[j];
            }
            __syncthreads();
        }
    }

    // ---------------- Epilogue: activations + k-reduction --------------------
    const float* bo = freq_bias + (size_t)k * 256;
    const float* bz = freq_bias + (size_t)(256 + k) * 256;
#pragma unroll
    for (int i = 0; i < 8; i++) {
        const int b = rg * 8 + i;
#pragma unroll
        for (int j = 0; j < 4; j++) {
            const int v = v0 + cg * 4 + j;
            const float o  = hsig(acc_o[i][j] + bo[v]);
            const float zz = o * tanhf(acc_z[i][j] + bz[v]);
            atomicAdd(&z_out[b * 256 + v], zz);
        }
    }
}

// ============================================================================
// launch
// ============================================================================
extern "C" void kernel_launch(void* const* d_in, const int* in_sizes, int n_in,
                              void* d_out, int out_size)
{
    const float* x        = (const float*)d_in[0];
    const float* t        = (const float*)d_in[1];
    const float* z_prev   = (const float*)d_in[2];
    const float* Im_prev  = (const float*)d_in[3];
    const float* Re_prev  = (const float*)d_in[4];
    const float* omg_prev = (const float*)d_in[5];
    const float* kern     = (const float*)d_in[6];
    const float* recur    = (const float*)d_in[7];
    const float* freq_k   = (const float*)d_in[8];
    const float* freq_ki  = (const float*)d_in[9];
    const float* bias     = (const float*)d_in[10];
    const float* freqb    = (const float*)d_in[11];

    float* out     = (float*)d_out;
    float* z_out   = out;                                  // (B,U)      32768
    float* im_out  = out + 32768;                          // (B,U,U)  8388608
    float* re_out  = out + 32768 + 8388608;                // (B,U,U)  8388608
    float* omg_out = out + 32768 + 2 * 8388608;            // (B,U)      32768

    cudaMemsetAsync(z_out, 0, 32768 * sizeof(float), 0);

    k_gates_gemm<<<dim3(20, 2), 256>>>(x, z_prev, kern, recur, bias);
    k_gates_ew<<<128, 256>>>(omg_prev, t, omg_out);
    k_reim<<<dim3(4, 4, 128), 256>>>(Re_prev, Im_prev, im_out, re_out);
    k_freq<<<dim3(256, 4), 256>>>(x, z_prev, freq_k, freq_ki, freqb, z_out);
}